// round 16
// baseline (speedup 1.0000x reference)
#include <cuda_runtime.h>
#include <cstdint>

#define NB 8
#define LQ 8192
#define SK 8192
#define HH 8
#define DD 32
#define NH (NB*HH)
#define EPSV 1e-6f

// pass1 (per-n): grid (CHUNKS, HH)
#define CHUNKS 32
#define SROWS (SK / CHUNKS)   // 256 s-rows per block
#define TS 64                 // tile rows
#define TILES (SROWS / TS)    // 4

// pass2 (per-n): grid (LQ/P2_L)
#define P2_THREADS 256
#define P2_L 32                       // l rows per block
#define QSTR 33                       // odd stride for q planes (LDS.32 reads)
#define KVSTR 36                      // 16B-aligned stride for kv rows
#define SQH_PLANE (P2_L * QSTR)       // 1056
#define SKV_PLANE (DD * KVSTR)        // 1152
#define P2_SMEM_FLOATS (HH*SQH_PLANE + HH*SKV_PLANE + HH*QSTR + P2_L*HH)
#define P2_SMEM_BYTES (P2_SMEM_FLOATS * 4)

// Scratch (device globals: no allocation allowed).
__device__ __align__(16) float g_KVpart[CHUNKS][NH][DD * DD];  // 8 MB
__device__ __align__(16) float g_KSpart[CHUNKS][NH][DD];       // 256 KB
__device__ __align__(16) float g_KV[NH * DD * DD];             // [nh][d][v]
__device__ __align__(16) float g_Ksum[NH * DD];                // [nh][d]

__device__ __forceinline__ float elu1(float x) {
    return x > 0.f ? x + 1.f : __expf(x);
}

__device__ __forceinline__ void fma2(unsigned long long &acc,
                                     unsigned long long a,
                                     unsigned long long b) {
    asm("fma.rn.f32x2 %0, %1, %2, %0;" : "+l"(acc) : "l"(a), "l"(b));
}
__device__ __forceinline__ unsigned long long pk(float x, float y) {
    unsigned long long r;
    asm("mov.b64 %0, {%1,%2};" : "=l"(r) : "f"(x), "f"(y));
    return r;
}
__device__ __forceinline__ float2 upk(unsigned long long v) {
    float2 r;
    asm("mov.b64 {%0,%1}, %2;" : "=f"(r.x), "=f"(r.y) : "l"(v));
    return r;
}

__device__ __forceinline__ void cp16(uint32_t smem_dst, const void* gmem_src) {
    asm volatile("cp.async.cg.shared.global [%0], [%1], 16;"
                 :: "r"(smem_dst), "l"(gmem_src));
}
__device__ __forceinline__ void cp_commit() {
    asm volatile("cp.async.commit_group;");
}
__device__ __forceinline__ void cp_wait0() {
    asm volatile("cp.async.wait_group 0;");
}

// ---------------------------------------------------------------------------
// Pass 1 (per-n): KVpart[chunk][n*HH+h] = sum_{s in chunk} outer(eluK_s, v_s)
// Structure identical to R14's measured-48.7us kernel; batch index n is a
// kernel argument, grid (CHUNKS, HH).
// ---------------------------------------------------------------------------
__global__ __launch_bounds__(256, 2) void pass1(const float* __restrict__ keys,
                                                const float* __restrict__ values,
                                                const int n) {
    __shared__ __align__(16) float sm[8192];
    __shared__ __align__(16) float4 sKsum[256];

    const int h = blockIdx.y;
    const int nh = n * HH + h;
    const int chunk = blockIdx.x;
    const int tid = threadIdx.x;
    const int w = tid >> 5, lane = tid & 31;
    const int rep = lane >> 4;
    const int dg = (lane >> 2) & 3;
    const int vg = lane & 3;
    const int r = tid >> 3;
    const int c4 = (tid & 7) * 4;

    unsigned long long acc[8][4];
#pragma unroll
    for (int i = 0; i < 8; ++i)
#pragma unroll
        for (int j = 0; j < 4; ++j) acc[i][j] = 0ull;
    float4 ksacc = make_float4(0.f, 0.f, 0.f, 0.f);

    const size_t base = ((size_t)n * SK * HH + h) * DD;
    const int rs = HH * DD;
    const int s_begin = chunk * SROWS;

    const float* kptr = keys   + base + (size_t)(s_begin + r) * rs + c4;
    const float* vptr = values + base + (size_t)(s_begin + r) * rs + c4;
    const size_t half_off = (size_t)32 * rs;

    const uint32_t vbase = (uint32_t)__cvta_generic_to_shared(&sm[4096]) +
                           (uint32_t)((r * 32 + c4) * 4);
    const uint32_t vbase2 = vbase + (uint32_t)(32 * 32 * 4);

    cp16(vbase, vptr);
    cp16(vbase2, vptr + half_off);
    cp_commit();
    float4 kqa = *(const float4*)kptr;
    float4 kqb = *(const float4*)(kptr + half_off);
    {
        const float a0 = elu1(kqa.x), a1 = elu1(kqa.y), a2 = elu1(kqa.z), a3 = elu1(kqa.w);
        const float b0 = elu1(kqb.x), b1 = elu1(kqb.y), b2 = elu1(kqb.z), b3 = elu1(kqb.w);
        ksacc.x += a0 + b0; ksacc.y += a1 + b1;
        ksacc.z += a2 + b2; ksacc.w += a3 + b3;
        *(float4*)&sm[r * 32 + c4]        = make_float4(a0, a1, a2, a3);
        *(float4*)&sm[(r + 32) * 32 + c4] = make_float4(b0, b1, b2, b3);
    }
    if (TILES > 1) {
        kqa = *(const float4*)(kptr + (size_t)TS * rs);
        kqb = *(const float4*)(kptr + (size_t)TS * rs + half_off);
    }
    cp_wait0();
    __syncthreads();

    for (int t = 0; t < TILES; ++t) {
        if (t + 1 < TILES) {
            const size_t adv = (size_t)(t + 1) * TS * rs;
            const uint32_t voff = (uint32_t)(((t + 1) & 1) * 2048 * 4);
            cp16(vbase + voff, vptr + adv);
            cp16(vbase2 + voff, vptr + adv + half_off);
            cp_commit();
        }

        {
            const float* kd = sm + (t & 1) * 2048;
            const float* vd = sm + 4096 + (t & 1) * 2048;
#pragma unroll
            for (int s2 = 0; s2 < 2; ++s2) {
                const int rA = w * 8 + s2 * 4 + rep * 2;
                const float4 ka0 = *(const float4*)&kd[rA * 32 + dg * 8];
                const float4 ka1 = *(const float4*)&kd[rA * 32 + dg * 8 + 4];
                const float4 kb0 = *(const float4*)&kd[(rA + 1) * 32 + dg * 8];
                const float4 kb1 = *(const float4*)&kd[(rA + 1) * 32 + dg * 8 + 4];
                const ulonglong2 va01 = *(const ulonglong2*)&vd[rA * 32 + vg * 8];
                const ulonglong2 va23 = *(const ulonglong2*)&vd[rA * 32 + vg * 8 + 4];
                const ulonglong2 vb01 = *(const ulonglong2*)&vd[(rA + 1) * 32 + vg * 8];
                const ulonglong2 vb23 = *(const ulonglong2*)&vd[(rA + 1) * 32 + vg * 8 + 4];
                const float kA[8] = {ka0.x, ka0.y, ka0.z, ka0.w, ka1.x, ka1.y, ka1.z, ka1.w};
                const float kB[8] = {kb0.x, kb0.y, kb0.z, kb0.w, kb1.x, kb1.y, kb1.z, kb1.w};
                const unsigned long long vA[4] = {va01.x, va01.y, va23.x, va23.y};
                const unsigned long long vB[4] = {vb01.x, vb01.y, vb23.x, vb23.y};
#pragma unroll
                for (int i = 0; i < 8; ++i) {
                    const unsigned long long kkA = pk(kA[i], kA[i]);
#pragma unroll
                    for (int j = 0; j < 4; ++j) fma2(acc[i][j], kkA, vA[j]);
                    const unsigned long long kkB = pk(kB[i], kB[i]);
#pragma unroll
                    for (int j = 0; j < 4; ++j) fma2(acc[i][j], kkB, vB[j]);
                }
            }
        }

        if (t + 1 < TILES) {
            float* kd1 = sm + ((t + 1) & 1) * 2048;
            const float a0 = elu1(kqa.x), a1 = elu1(kqa.y), a2 = elu1(kqa.z), a3 = elu1(kqa.w);
            const float b0 = elu1(kqb.x), b1 = elu1(kqb.y), b2 = elu1(kqb.z), b3 = elu1(kqb.w);
            ksacc.x += a0 + b0; ksacc.y += a1 + b1;
            ksacc.z += a2 + b2; ksacc.w += a3 + b3;
            *(float4*)&kd1[r * 32 + c4]        = make_float4(a0, a1, a2, a3);
            *(float4*)&kd1[(r + 32) * 32 + c4] = make_float4(b0, b1, b2, b3);
            if (t + 2 < TILES) {
                const size_t adv2 = (size_t)(t + 2) * TS * rs;
                kqa = *(const float4*)(kptr + adv2);
                kqb = *(const float4*)(kptr + adv2 + half_off);
            }
            cp_wait0();
            __syncthreads();
        }
    }
    __syncthreads();

#pragma unroll
    for (int i = 0; i < 8; ++i)
#pragma unroll
        for (int j = 0; j < 4; ++j) {
            float2 a = upk(acc[i][j]);
            a.x += __shfl_down_sync(0xffffffffu, a.x, 16);
            a.y += __shfl_down_sync(0xffffffffu, a.y, 16);
            acc[i][j] = pk(a.x, a.y);
        }

    if (rep == 0) {
#pragma unroll
        for (int i = 0; i < 8; ++i)
#pragma unroll
            for (int j = 0; j < 4; ++j)
                *(unsigned long long*)&sm[w * 1024 + (dg * 8 + i) * 32 + vg * 8 + 2 * j]
                    = acc[i][j];
    }
    __syncthreads();
    {
        float4 ssum = make_float4(0.f, 0.f, 0.f, 0.f);
#pragma unroll
        for (int ww = 0; ww < 8; ++ww) {
            const float4 vv = *(const float4*)&sm[ww * 1024 + tid * 4];
            ssum.x += vv.x; ssum.y += vv.y; ssum.z += vv.z; ssum.w += vv.w;
        }
        *(float4*)&g_KVpart[chunk][nh][tid * 4] = ssum;
    }

    sKsum[tid] = ksacc;
    __syncthreads();
    if (tid < DD) {
        const int cgrp = tid >> 2;
        const int comp = tid & 3;
        float ssum = 0.f;
        for (int k = 0; k < 32; ++k) {
            const float4 vk = sKsum[cgrp + 8 * k];
            ssum += (comp == 0) ? vk.x : (comp == 1) ? vk.y : (comp == 2) ? vk.z : vk.w;
        }
        g_KSpart[chunk][nh][tid] = ssum;
    }
}

// ---------------------------------------------------------------------------
// Reduce (per-n): fold 32 chunk partials -> g_KV, g_Ksum for heads of n.
// ---------------------------------------------------------------------------
__global__ __launch_bounds__(256) void reduce_kernel(const int n) {
    const int nh = n * HH + blockIdx.x;
    const int tid = threadIdx.x;
    float4 s = make_float4(0.f, 0.f, 0.f, 0.f);
#pragma unroll
    for (int c = 0; c < CHUNKS; ++c) {
        const float4 p = *(const float4*)&g_KVpart[c][nh][tid * 4];
        s.x += p.x; s.y += p.y; s.z += p.z; s.w += p.w;
    }
    *(float4*)&g_KV[nh * DD * DD + tid * 4] = s;
    if (tid < DD) {
        float ks = 0.f;
#pragma unroll
        for (int c = 0; c < CHUNKS; ++c) ks += g_KSpart[c][nh][tid];
        g_Ksum[nh * DD + tid] = ks;
    }
}

// ---------------------------------------------------------------------------
// Pass 2 (per-n): R12's measured-57.6us kernel; n as argument, grid (LQ/32).
// ---------------------------------------------------------------------------
__global__ __launch_bounds__(P2_THREADS, 3) void pass2(const float* __restrict__ queries,
                                                       float* __restrict__ out,
                                                       const int n) {
    extern __shared__ __align__(16) float dyn[];
    float* sQ   = dyn;                               // 8 heads x 32 l x QSTR
    float* sKV  = dyn + HH * SQH_PLANE;              // 8 heads x 32 d x KVSTR
    float* sKs  = sKV + HH * SKV_PLANE;              // 8 heads x QSTR
    float* sInv = sKs + HH * QSTR;                   // 8 heads x 32 l

    const int l0 = blockIdx.x * P2_L;
    const int tid = threadIdx.x;
    const int w = tid >> 5, lane = tid & 31;
    const int lg = lane >> 2;         // l-group: l = lg*4 + i
    const int vg = lane & 3;          // v-group: v = vg*8 + 2j(+1)

    const float* kvsrc = &g_KV[(size_t)(n * HH) * DD * DD];
#pragma unroll
    for (int i = 0; i < 8; ++i) {
        const int f4 = tid + P2_THREADS * i;         // 0..2047
        const int hh = f4 >> 8;
        const int d  = (f4 >> 3) & 31;
        const int c  = (f4 & 7) * 4;
        *(float4*)&sKV[hh * SKV_PLANE + d * KVSTR + c] = *(const float4*)(kvsrc + f4 * 4);
    }
    {
        const int hh = tid >> 5, d = tid & 31;
        sKs[hh * QSTR + d] = g_Ksum[(n * HH + hh) * DD + d];
    }

    const float* qsrc = queries + ((size_t)n * LQ + l0) * (HH * DD);
#pragma unroll
    for (int i = 0; i < 8; ++i) {
        const int f4 = tid + P2_THREADS * i;         // 0..2047
        const float4 qv = *(const float4*)(qsrc + (size_t)f4 * 4);
        const int l  = f4 >> 6;
        const int hh = (f4 >> 3) & 7;
        const int c  = (f4 & 7) * 4;
        float* dst = &sQ[hh * SQH_PLANE + l * QSTR + c];
        dst[0] = elu1(qv.x); dst[1] = elu1(qv.y);
        dst[2] = elu1(qv.z); dst[3] = elu1(qv.w);
    }
    __syncthreads();

    {
        const float* qrow = &sQ[w * SQH_PLANE + lane * QSTR];
        const float* ksh  = &sKs[w * QSTR];
        float z = EPSV;
#pragma unroll
        for (int d = 0; d < DD; ++d) z += qrow[d] * ksh[d];
        sInv[w * P2_L + lane] = 1.0f / z;
    }
    __syncthreads();

    unsigned long long acc[4][4];     // [i:l][j:v-pair]
#pragma unroll
    for (int i = 0; i < 4; ++i)
#pragma unroll
        for (int j = 0; j < 4; ++j) acc[i][j] = 0ull;

    const float* qpl = &sQ[w * SQH_PLANE + lg * 4 * QSTR];
    const float* kvp = &sKV[w * SKV_PLANE + vg * 8];
#pragma unroll
    for (int d = 0; d < DD; ++d) {
        const float q0 = qpl[0 * QSTR + d];
        const float q1 = qpl[1 * QSTR + d];
        const float q2 = qpl[2 * QSTR + d];
        const float q3 = qpl[3 * QSTR + d];
        const ulonglong2 ka = *(const ulonglong2*)(kvp + d * KVSTR);
        const ulonglong2 kb = *(const ulonglong2*)(kvp + d * KVSTR + 4);
        const unsigned long long qq[4] = {pk(q0, q0), pk(q1, q1), pk(q2, q2), pk(q3, q3)};
        const unsigned long long vv[4] = {ka.x, ka.y, kb.x, kb.y};
#pragma unroll
        for (int i = 0; i < 4; ++i)
#pragma unroll
            for (int j = 0; j < 4; ++j) fma2(acc[i][j], qq[i], vv[j]);
    }

#pragma unroll
    for (int i = 0; i < 4; ++i) {
        const int l = lg * 4 + i;
        const float inv = sInv[w * P2_L + l];
        const float2 a0 = upk(acc[i][0]);
        const float2 a1 = upk(acc[i][1]);
        const float2 a2 = upk(acc[i][2]);
        const float2 a3 = upk(acc[i][3]);
        float* orow = out + (((size_t)n * LQ + l0 + l) * HH + w) * DD + vg * 8;
        *(float4*)(orow)     = make_float4(a0.x * inv, a0.y * inv, a1.x * inv, a1.y * inv);
        *(float4*)(orow + 4) = make_float4(a2.x * inv, a2.y * inv, a3.x * inv, a3.y * inv);
    }
}

// ---------------------------------------------------------------------------
// Launch: per-n pipeline across two streams.
//   stream0: p1(0) r(0) | p1(1) r(1) | ... | p1(7) r(7)
//   stream2:        p2(0)       | p2(1) | ...      | p2(7)
// pass2(n) depends on reduce(n) via event; stream0 joins all pass2 at the end.
// Streams/events are created once on the first (eager, pre-capture) call;
// the captured graph is identical on every capture.
// ---------------------------------------------------------------------------
extern "C" void kernel_launch(void* const* d_in, const int* in_sizes, int n_in,
                              void* d_out, int out_size) {
    (void)in_sizes; (void)n_in; (void)out_size;
    const float* q = (const float*)d_in[0];
    const float* k = (const float*)d_in[1];
    const float* v = (const float*)d_in[2];
    float* out = (float*)d_out;

    static cudaStream_t s2 = nullptr;
    static cudaEvent_t evR[NB];
    static cudaEvent_t evT[NB];
    if (s2 == nullptr) {
        cudaStreamCreateWithFlags(&s2, cudaStreamNonBlocking);
        for (int i = 0; i < NB; ++i) {
            cudaEventCreateWithFlags(&evR[i], cudaEventDisableTiming);
            cudaEventCreateWithFlags(&evT[i], cudaEventDisableTiming);
        }
    }
    cudaFuncSetAttribute(pass2, cudaFuncAttributeMaxDynamicSharedMemorySize, P2_SMEM_BYTES);

    for (int n = 0; n < NB; ++n) {
        pass1<<<dim3(CHUNKS, HH), 256>>>(k, v, n);
        reduce_kernel<<<HH, 256>>>(n);
        cudaEventRecord(evR[n], 0);
        cudaStreamWaitEvent(s2, evR[n], 0);
        pass2<<<LQ / P2_L, P2_THREADS, P2_SMEM_BYTES, s2>>>(q, out, n);
        cudaEventRecord(evT[n], s2);
    }
    for (int n = 0; n < NB; ++n) cudaStreamWaitEvent(0, evT[n], 0);
}

// round 17
// speedup vs baseline: 1.8268x; 1.8268x over previous
#include <cuda_runtime.h>
#include <cstdint>

#define NB 8
#define LQ 8192
#define SK 8192
#define HH 8
#define DD 32
#define NH (NB*HH)
#define EPSV 1e-6f

// pass1
#define CHUNKS 16
#define SROWS (SK / CHUNKS)   // 512 s-rows per block
#define TS 64                 // tile rows
#define TILES (SROWS / TS)    // 8

// pass2
#define P2_THREADS 256
#define P2_L 32                       // l rows per block
#define QSTR 33                       // odd stride for q planes (LDS.32 reads)
#define KVSTR 36                      // 16B-aligned stride for kv rows
#define SQH_PLANE (P2_L * QSTR)       // 1056
#define SKV_PLANE (DD * KVSTR)        // 1152
#define P2_SMEM_FLOATS (HH*SQH_PLANE + HH*SKV_PLANE + HH*QSTR + P2_L*HH)
#define P2_SMEM_BYTES (P2_SMEM_FLOATS * 4)

// Scratch (device globals: no allocation allowed).
__device__ __align__(16) float g_KVpart[CHUNKS][NH][DD * DD];  // 4 MB
__device__ __align__(16) float g_KSpart[CHUNKS][NH][DD];       // 128 KB
__device__ __align__(16) float g_KV[NH * DD * DD];             // [nh][d][v]
__device__ __align__(16) float g_Ksum[NH * DD];                // [nh][d]

__device__ __forceinline__ float elu1(float x) {
    return x > 0.f ? x + 1.f : __expf(x);
}

__device__ __forceinline__ void fma2(unsigned long long &acc,
                                     unsigned long long a,
                                     unsigned long long b) {
    asm("fma.rn.f32x2 %0, %1, %2, %0;" : "+l"(acc) : "l"(a), "l"(b));
}
__device__ __forceinline__ unsigned long long pk(float x, float y) {
    unsigned long long r;
    asm("mov.b64 %0, {%1,%2};" : "=l"(r) : "f"(x), "f"(y));
    return r;
}
__device__ __forceinline__ float2 upk(unsigned long long v) {
    float2 r;
    asm("mov.b64 {%0,%1}, %2;" : "=f"(r.x), "=f"(r.y) : "l"(v));
    return r;
}

__device__ __forceinline__ void cp16(uint32_t smem_dst, const void* gmem_src) {
    asm volatile("cp.async.cg.shared.global [%0], [%1], 16;"
                 :: "r"(smem_dst), "l"(gmem_src));
}
__device__ __forceinline__ void cp_commit() {
    asm volatile("cp.async.commit_group;");
}
__device__ __forceinline__ void cp_wait0() {
    asm volatile("cp.async.wait_group 0;");
}

// ---------------------------------------------------------------------------
// Pass 1: KVpart[chunk][nh] = sum_{s in chunk} outer(eluK_s, v_s)
// R14's kernel, byte-identical (measured 48.7us).
// ---------------------------------------------------------------------------
__global__ __launch_bounds__(256, 2) void pass1(const float* __restrict__ keys,
                                                const float* __restrict__ values) {
    __shared__ __align__(16) float sm[8192];
    __shared__ __align__(16) float4 sKsum[256];

    const int nh = blockIdx.y;
    const int n = nh / HH, h = nh % HH;
    const int chunk = blockIdx.x;
    const int tid = threadIdx.x;
    const int w = tid >> 5, lane = tid & 31;
    const int rep = lane >> 4;
    const int dg = (lane >> 2) & 3;
    const int vg = lane & 3;
    const int r = tid >> 3;
    const int c4 = (tid & 7) * 4;

    unsigned long long acc[8][4];
#pragma unroll
    for (int i = 0; i < 8; ++i)
#pragma unroll
        for (int j = 0; j < 4; ++j) acc[i][j] = 0ull;
    float4 ksacc = make_float4(0.f, 0.f, 0.f, 0.f);

    const size_t base = ((size_t)n * SK * HH + h) * DD;
    const int rs = HH * DD;
    const int s_begin = chunk * SROWS;

    const float* kptr = keys   + base + (size_t)(s_begin + r) * rs + c4;
    const float* vptr = values + base + (size_t)(s_begin + r) * rs + c4;
    const size_t half_off = (size_t)32 * rs;

    const uint32_t vbase = (uint32_t)__cvta_generic_to_shared(&sm[4096]) +
                           (uint32_t)((r * 32 + c4) * 4);
    const uint32_t vbase2 = vbase + (uint32_t)(32 * 32 * 4);

    cp16(vbase, vptr);
    cp16(vbase2, vptr + half_off);
    cp_commit();
    float4 kqa = *(const float4*)kptr;
    float4 kqb = *(const float4*)(kptr + half_off);
    {
        const float a0 = elu1(kqa.x), a1 = elu1(kqa.y), a2 = elu1(kqa.z), a3 = elu1(kqa.w);
        const float b0 = elu1(kqb.x), b1 = elu1(kqb.y), b2 = elu1(kqb.z), b3 = elu1(kqb.w);
        ksacc.x += a0 + b0; ksacc.y += a1 + b1;
        ksacc.z += a2 + b2; ksacc.w += a3 + b3;
        *(float4*)&sm[r * 32 + c4]        = make_float4(a0, a1, a2, a3);
        *(float4*)&sm[(r + 32) * 32 + c4] = make_float4(b0, b1, b2, b3);
    }
    if (TILES > 1) {
        kqa = *(const float4*)(kptr + (size_t)TS * rs);
        kqb = *(const float4*)(kptr + (size_t)TS * rs + half_off);
    }
    cp_wait0();
    __syncthreads();

    for (int t = 0; t < TILES; ++t) {
        if (t + 1 < TILES) {
            const size_t adv = (size_t)(t + 1) * TS * rs;
            const uint32_t voff = (uint32_t)(((t + 1) & 1) * 2048 * 4);
            cp16(vbase + voff, vptr + adv);
            cp16(vbase2 + voff, vptr + adv + half_off);
            cp_commit();
        }

        {
            const float* kd = sm + (t & 1) * 2048;
            const float* vd = sm + 4096 + (t & 1) * 2048;
#pragma unroll
            for (int s2 = 0; s2 < 2; ++s2) {
                const int rA = w * 8 + s2 * 4 + rep * 2;
                const float4 ka0 = *(const float4*)&kd[rA * 32 + dg * 8];
                const float4 ka1 = *(const float4*)&kd[rA * 32 + dg * 8 + 4];
                const float4 kb0 = *(const float4*)&kd[(rA + 1) * 32 + dg * 8];
                const float4 kb1 = *(const float4*)&kd[(rA + 1) * 32 + dg * 8 + 4];
                const ulonglong2 va01 = *(const ulonglong2*)&vd[rA * 32 + vg * 8];
                const ulonglong2 va23 = *(const ulonglong2*)&vd[rA * 32 + vg * 8 + 4];
                const ulonglong2 vb01 = *(const ulonglong2*)&vd[(rA + 1) * 32 + vg * 8];
                const ulonglong2 vb23 = *(const ulonglong2*)&vd[(rA + 1) * 32 + vg * 8 + 4];
                const float kA[8] = {ka0.x, ka0.y, ka0.z, ka0.w, ka1.x, ka1.y, ka1.z, ka1.w};
                const float kB[8] = {kb0.x, kb0.y, kb0.z, kb0.w, kb1.x, kb1.y, kb1.z, kb1.w};
                const unsigned long long vA[4] = {va01.x, va01.y, va23.x, va23.y};
                const unsigned long long vB[4] = {vb01.x, vb01.y, vb23.x, vb23.y};
#pragma unroll
                for (int i = 0; i < 8; ++i) {
                    const unsigned long long kkA = pk(kA[i], kA[i]);
#pragma unroll
                    for (int j = 0; j < 4; ++j) fma2(acc[i][j], kkA, vA[j]);
                    const unsigned long long kkB = pk(kB[i], kB[i]);
#pragma unroll
                    for (int j = 0; j < 4; ++j) fma2(acc[i][j], kkB, vB[j]);
                }
            }
        }

        if (t + 1 < TILES) {
            float* kd1 = sm + ((t + 1) & 1) * 2048;
            const float a0 = elu1(kqa.x), a1 = elu1(kqa.y), a2 = elu1(kqa.z), a3 = elu1(kqa.w);
            const float b0 = elu1(kqb.x), b1 = elu1(kqb.y), b2 = elu1(kqb.z), b3 = elu1(kqb.w);
            ksacc.x += a0 + b0; ksacc.y += a1 + b1;
            ksacc.z += a2 + b2; ksacc.w += a3 + b3;
            *(float4*)&kd1[r * 32 + c4]        = make_float4(a0, a1, a2, a3);
            *(float4*)&kd1[(r + 32) * 32 + c4] = make_float4(b0, b1, b2, b3);
            if (t + 2 < TILES) {
                const size_t adv2 = (size_t)(t + 2) * TS * rs;
                kqa = *(const float4*)(kptr + adv2);
                kqb = *(const float4*)(kptr + adv2 + half_off);
            }
            cp_wait0();
            __syncthreads();
        }
    }
    __syncthreads();

#pragma unroll
    for (int i = 0; i < 8; ++i)
#pragma unroll
        for (int j = 0; j < 4; ++j) {
            float2 a = upk(acc[i][j]);
            a.x += __shfl_down_sync(0xffffffffu, a.x, 16);
            a.y += __shfl_down_sync(0xffffffffu, a.y, 16);
            acc[i][j] = pk(a.x, a.y);
        }

    if (rep == 0) {
#pragma unroll
        for (int i = 0; i < 8; ++i)
#pragma unroll
            for (int j = 0; j < 4; ++j)
                *(unsigned long long*)&sm[w * 1024 + (dg * 8 + i) * 32 + vg * 8 + 2 * j]
                    = acc[i][j];
    }
    __syncthreads();
    {
        float4 ssum = make_float4(0.f, 0.f, 0.f, 0.f);
#pragma unroll
        for (int ww = 0; ww < 8; ++ww) {
            const float4 vv = *(const float4*)&sm[ww * 1024 + tid * 4];
            ssum.x += vv.x; ssum.y += vv.y; ssum.z += vv.z; ssum.w += vv.w;
        }
        *(float4*)&g_KVpart[chunk][nh][tid * 4] = ssum;
    }

    sKsum[tid] = ksacc;
    __syncthreads();
    if (tid < DD) {
        const int cgrp = tid >> 2;
        const int comp = tid & 3;
        float ssum = 0.f;
        for (int k = 0; k < 32; ++k) {
            const float4 vk = sKsum[cgrp + 8 * k];
            ssum += (comp == 0) ? vk.x : (comp == 1) ? vk.y : (comp == 2) ? vk.z : vk.w;
        }
        g_KSpart[chunk][nh][tid] = ssum;
    }
}

// ---------------------------------------------------------------------------
// Reduce: fold 16 chunk partials -> g_KV, g_Ksum.
// ---------------------------------------------------------------------------
__global__ __launch_bounds__(256) void reduce_kernel() {
    const int nh = blockIdx.x;
    const int tid = threadIdx.x;
    float4 s = make_float4(0.f, 0.f, 0.f, 0.f);
#pragma unroll
    for (int c = 0; c < CHUNKS; ++c) {
        const float4 p = *(const float4*)&g_KVpart[c][nh][tid * 4];
        s.x += p.x; s.y += p.y; s.z += p.z; s.w += p.w;
    }
    *(float4*)&g_KV[nh * DD * DD + tid * 4] = s;
    if (tid < DD) {
        float ks = 0.f;
#pragma unroll
        for (int c = 0; c < CHUNKS; ++c) ks += g_KSpart[c][nh][tid];
        g_Ksum[nh * DD + tid] = ks;
    }
}

// ---------------------------------------------------------------------------
// Pass 2: R12's kernel, byte-identical (decomposition-measured ~57.6us).
// ---------------------------------------------------------------------------
__global__ __launch_bounds__(P2_THREADS, 3) void pass2(const float* __restrict__ queries,
                                                       float* __restrict__ out) {
    extern __shared__ __align__(16) float dyn[];
    float* sQ   = dyn;                               // 8 heads x 32 l x QSTR
    float* sKV  = dyn + HH * SQH_PLANE;              // 8 heads x 32 d x KVSTR
    float* sKs  = sKV + HH * SKV_PLANE;              // 8 heads x QSTR
    float* sInv = sKs + HH * QSTR;                   // 8 heads x 32 l

    const int n  = blockIdx.y;
    const int l0 = blockIdx.x * P2_L;
    const int tid = threadIdx.x;
    const int w = tid >> 5, lane = tid & 31;
    const int lg = lane >> 2;         // l-group: l = lg*4 + i
    const int vg = lane & 3;          // v-group: v = vg*8 + 2j(+1)

    const float* kvsrc = &g_KV[(size_t)(n * HH) * DD * DD];
#pragma unroll
    for (int i = 0; i < 8; ++i) {
        const int f4 = tid + P2_THREADS * i;         // 0..2047
        const int hh = f4 >> 8;
        const int d  = (f4 >> 3) & 31;
        const int c  = (f4 & 7) * 4;
        *(float4*)&sKV[hh * SKV_PLANE + d * KVSTR + c] = *(const float4*)(kvsrc + f4 * 4);
    }
    {
        const int hh = tid >> 5, d = tid & 31;
        sKs[hh * QSTR + d] = g_Ksum[(n * HH + hh) * DD + d];
    }

    const float* qsrc = queries + ((size_t)n * LQ + l0) * (HH * DD);
#pragma unroll
    for (int i = 0; i < 8; ++i) {
        const int f4 = tid + P2_THREADS * i;         // 0..2047
        const float4 qv = *(const float4*)(qsrc + (size_t)f4 * 4);
        const int l  = f4 >> 6;
        const int hh = (f4 >> 3) & 7;
        const int c  = (f4 & 7) * 4;
        float* dst = &sQ[hh * SQH_PLANE + l * QSTR + c];
        dst[0] = elu1(qv.x); dst[1] = elu1(qv.y);
        dst[2] = elu1(qv.z); dst[3] = elu1(qv.w);
    }
    __syncthreads();

    {
        const float* qrow = &sQ[w * SQH_PLANE + lane * QSTR];
        const float* ksh  = &sKs[w * QSTR];
        float z = EPSV;
#pragma unroll
        for (int d = 0; d < DD; ++d) z += qrow[d] * ksh[d];
        sInv[w * P2_L + lane] = 1.0f / z;
    }
    __syncthreads();

    unsigned long long acc[4][4];     // [i:l][j:v-pair]
#pragma unroll
    for (int i = 0; i < 4; ++i)
#pragma unroll
        for (int j = 0; j < 4; ++j) acc[i][j] = 0ull;

    const float* qpl = &sQ[w * SQH_PLANE + lg * 4 * QSTR];
    const float* kvp = &sKV[w * SKV_PLANE + vg * 8];
#pragma unroll 4
    for (int d = 0; d < DD; ++d) {
        const float q0 = qpl[0 * QSTR + d];
        const float q1 = qpl[1 * QSTR + d];
        const float q2 = qpl[2 * QSTR + d];
        const float q3 = qpl[3 * QSTR + d];
        const ulonglong2 ka = *(const ulonglong2*)(kvp + d * KVSTR);
        const ulonglong2 kb = *(const ulonglong2*)(kvp + d * KVSTR + 4);
        const unsigned long long qq[4] = {pk(q0, q0), pk(q1, q1), pk(q2, q2), pk(q3, q3)};
        const unsigned long long vv[4] = {ka.x, ka.y, kb.x, kb.y};
#pragma unroll
        for (int i = 0; i < 4; ++i)
#pragma unroll
            for (int j = 0; j < 4; ++j) fma2(acc[i][j], qq[i], vv[j]);
    }

#pragma unroll
    for (int i = 0; i < 4; ++i) {
        const int l = lg * 4 + i;
        const float inv = sInv[w * P2_L + l];
        const float2 a0 = upk(acc[i][0]);
        const float2 a1 = upk(acc[i][1]);
        const float2 a2 = upk(acc[i][2]);
        const float2 a3 = upk(acc[i][3]);
        float* orow = out + (((size_t)n * LQ + l0 + l) * HH + w) * DD + vg * 8;
        *(float4*)(orow)     = make_float4(a0.x * inv, a0.y * inv, a1.x * inv, a1.y * inv);
        *(float4*)(orow + 4) = make_float4(a2.x * inv, a2.y * inv, a3.x * inv, a3.y * inv);
    }
}

extern "C" void kernel_launch(void* const* d_in, const int* in_sizes, int n_in,
                              void* d_out, int out_size) {
    (void)in_sizes; (void)n_in; (void)out_size;
    const float* q = (const float*)d_in[0];
    const float* k = (const float*)d_in[1];
    const float* v = (const float*)d_in[2];
    float* out = (float*)d_out;

    pass1<<<dim3(CHUNKS, NH), 256>>>(k, v);
    reduce_kernel<<<NH, 256>>>();
    cudaFuncSetAttribute(pass2, cudaFuncAttributeMaxDynamicSharedMemorySize, P2_SMEM_BYTES);
    pass2<<<dim3(LQ / P2_L, NB), P2_THREADS, P2_SMEM_BYTES>>>(q, out);
}